// round 2
// baseline (speedup 1.0000x reference)
#include <cuda_runtime.h>

#define DD 256
#define KK 32
#define NWARPS 8
#define ROWS_PER_WARP 8          // processed 2 at a time
#define ROWS_PER_BLOCK (NWARPS * ROWS_PER_WARP)   // 64

typedef unsigned long long u64;

__device__ __forceinline__ u64 pack2(float lo, float hi) {
    u64 r;
    asm("mov.b64 %0, {%1, %2};" : "=l"(r) : "f"(lo), "f"(hi));
    return r;
}
__device__ __forceinline__ float2 unpack2(u64 v) {
    float2 f;
    asm("mov.b64 {%0, %1}, %2;" : "=f"(f.x), "=f"(f.y) : "l"(v));
    return f;
}
__device__ __forceinline__ u64 fma2(u64 a, u64 b, u64 c) {
    u64 d;
    asm("fma.rn.f32x2 %0, %1, %2, %3;" : "=l"(d) : "l"(a), "l"(b), "l"(c));
    return d;
}
__device__ __forceinline__ u64 add2(u64 a, u64 b) {
    u64 d;
    asm("add.rn.f32x2 %0, %1, %2;" : "=l"(d) : "l"(a), "l"(b));
    return d;
}

__global__ void __launch_bounds__(256)
hh_kernel(const float* __restrict__ in,
          const float* __restrict__ qv,
          float* __restrict__ out,
          int n_rows) {
    __shared__ float qs[KK * DD];      // 32 KB
    __shared__ float scale[KK];

    const int tid = threadIdx.x;

    // Stage q vectors into SMEM (vectorized)
    {
        const float4* qg = (const float4*)qv;
        float4* qsh = (float4*)qs;
        #pragma unroll
        for (int i = tid; i < KK * DD / 4; i += 256) qsh[i] = qg[i];
    }
    __syncthreads();

    // Compute 2/||q_k||^2 (one thread per k; tiny one-time cost per block)
    if (tid < KK) {
        float s = 0.f;
        #pragma unroll 8
        for (int d = 0; d < DD; d++) { float v = qs[tid * DD + d]; s = fmaf(v, v, s); }
        scale[tid] = 2.0f / s;
    }
    __syncthreads();

    const int warp = tid >> 5;
    const int lane = tid & 31;
    const long long base_row = (long long)blockIdx.x * ROWS_PER_BLOCK
                             + (long long)warp * ROWS_PER_WARP;
    const float4* q4 = (const float4*)qs;

    for (int rp = 0; rp < ROWS_PER_WARP; rp += 2) {
        long long rowA = base_row + rp;
        if (rowA >= n_rows) break;
        long long rowB = rowA + 1;
        bool hasB = (rowB < n_rows);
        long long rB = hasB ? rowB : rowA;

        // Load rows: lane owns elements [4*lane,4*lane+4) and [128+4*lane, ...)
        const float4* xa = (const float4*)(in + rowA * DD);
        const float4* xb = (const float4*)(in + rB * DD);
        float4 a0 = xa[lane], a1 = xa[lane + 32];
        float4 b0 = xb[lane], b1 = xb[lane + 32];

        u64 A0 = pack2(a0.x, a0.y), A1 = pack2(a0.z, a0.w);
        u64 A2 = pack2(a1.x, a1.y), A3 = pack2(a1.z, a1.w);
        u64 B0 = pack2(b0.x, b0.y), B1 = pack2(b0.z, b0.w);
        u64 B2 = pack2(b1.x, b1.y), B3 = pack2(b1.z, b1.w);

        #pragma unroll 4
        for (int k = 0; k < KK; k++) {
            float4 qk0 = q4[k * 64 + lane];
            float4 qk1 = q4[k * 64 + lane + 32];
            u64 Q0 = pack2(qk0.x, qk0.y), Q1 = pack2(qk0.z, qk0.w);
            u64 Q2 = pack2(qk1.x, qk1.y), Q3 = pack2(qk1.z, qk1.w);

            // Packed partial dots (2 chains each for ILP)
            u64 da0 = fma2(A0, Q0, 0ull); da0 = fma2(A2, Q2, da0);
            u64 da1 = fma2(A1, Q1, 0ull); da1 = fma2(A3, Q3, da1);
            u64 db0 = fma2(B0, Q0, 0ull); db0 = fma2(B2, Q2, db0);
            u64 db1 = fma2(B1, Q1, 0ull); db1 = fma2(B3, Q3, db1);
            float2 fa = unpack2(add2(da0, da1));
            float2 fb = unpack2(add2(db0, db1));
            float sA = fa.x + fa.y;
            float sB = fb.x + fb.y;

            // Butterfly reduction across warp (both rows in flight)
            #pragma unroll
            for (int off = 16; off > 0; off >>= 1) {
                sA += __shfl_xor_sync(0xFFFFFFFFu, sA, off);
                sB += __shfl_xor_sync(0xFFFFFFFFu, sB, off);
            }

            float sc = scale[k];
            float cA = -sA * sc;
            float cB = -sB * sc;
            u64 CA = pack2(cA, cA);
            u64 CB = pack2(cB, cB);

            // Rank-1 update: x += c * q  (packed)
            A0 = fma2(CA, Q0, A0); A1 = fma2(CA, Q1, A1);
            A2 = fma2(CA, Q2, A2); A3 = fma2(CA, Q3, A3);
            B0 = fma2(CB, Q0, B0); B1 = fma2(CB, Q1, B1);
            B2 = fma2(CB, Q2, B2); B3 = fma2(CB, Q3, B3);
        }

        // Store
        float2 t;
        float4 o;
        t = unpack2(A0); o.x = t.x; o.y = t.y;
        t = unpack2(A1); o.z = t.x; o.w = t.y;
        ((float4*)(out + rowA * DD))[lane] = o;
        t = unpack2(A2); o.x = t.x; o.y = t.y;
        t = unpack2(A3); o.z = t.x; o.w = t.y;
        ((float4*)(out + rowA * DD))[lane + 32] = o;

        if (hasB) {
            t = unpack2(B0); o.x = t.x; o.y = t.y;
            t = unpack2(B1); o.z = t.x; o.w = t.y;
            ((float4*)(out + rowB * DD))[lane] = o;
            t = unpack2(B2); o.x = t.x; o.y = t.y;
            t = unpack2(B3); o.z = t.x; o.w = t.y;
            ((float4*)(out + rowB * DD))[lane + 32] = o;
        }
    }
}

__global__ void zero_tail_kernel(float* __restrict__ out, long long start, long long end) {
    long long i = start + (long long)blockIdx.x * blockDim.x + threadIdx.x;
    if (i < end) out[i] = 0.0f;
}

extern "C" void kernel_launch(void* const* d_in, const int* in_sizes, int n_in,
                              void* d_out, int out_size) {
    const float* inp = (const float*)d_in[0];   // inputs  [N, 256]
    const float* qv  = (const float*)d_in[1];   // q_vectors [32, 256]
    float* out = (float*)d_out;

    int n_rows = in_sizes[0] / DD;

    int grid = (n_rows + ROWS_PER_BLOCK - 1) / ROWS_PER_BLOCK;
    hh_kernel<<<grid, 256>>>(inp, qv, out, n_rows);

    long long nd = (long long)n_rows * DD;
    long long total = (long long)out_size;
    if (total > nd) {
        long long tail = total - nd;
        int zgrid = (int)((tail + 255) / 256);
        zero_tail_kernel<<<zgrid, 256>>>(out, nd, total);
    }
}

// round 4
// speedup vs baseline: 1.3226x; 1.3226x over previous
#include <cuda_runtime.h>
#include <cuda_bf16.h>
#include <cstdint>

#define DDIM 256
#define KREF 32
#define MT   128

// ---------------- device scratch (no allocation) ----------------
__device__ __align__(16) float         g_W[KREF * DDIM];
__device__ __align__(16) __nv_bfloat16 g_Uh[KREF * DDIM];   // [k][d]  (B operand GEMM1: rows=n(refl), cols=k(d))
__device__ __align__(16) __nv_bfloat16 g_Ul[KREF * DDIM];
__device__ __align__(16) __nv_bfloat16 g_Qh[DDIM * KREF];   // [d][k]  (B operand GEMM2: rows=n(d), cols=k(refl))
__device__ __align__(16) __nv_bfloat16 g_Ql[DDIM * KREF];

// ---------------- helpers ----------------
__device__ __forceinline__ uint32_t smem_u32(const void* p) {
    uint32_t a;
    asm("{ .reg .u64 t; cvta.to.shared.u64 t, %1; cvt.u32.u64 %0, t; }" : "=r"(a) : "l"(p));
    return a;
}
__device__ __forceinline__ void ldsm4(uint32_t& r0, uint32_t& r1, uint32_t& r2, uint32_t& r3,
                                      uint32_t addr) {
    asm volatile("ldmatrix.sync.aligned.m8n8.x4.shared.b16 {%0,%1,%2,%3}, [%4];"
                 : "=r"(r0), "=r"(r1), "=r"(r2), "=r"(r3) : "r"(addr));
}
__device__ __forceinline__ void mma16816(float* d, const uint32_t* a, uint32_t b0, uint32_t b1) {
    asm volatile(
        "mma.sync.aligned.m16n8k16.row.col.f32.bf16.bf16.f32 "
        "{%0,%1,%2,%3},{%4,%5,%6,%7},{%8,%9},{%0,%1,%2,%3};"
        : "+f"(d[0]), "+f"(d[1]), "+f"(d[2]), "+f"(d[3])
        : "r"(a[0]), "r"(a[1]), "r"(a[2]), "r"(a[3]), "r"(b0), "r"(b1));
}
__device__ __forceinline__ uint32_t pack_bf16x2(float x, float y) {
    __nv_bfloat162 p = __halves2bfloat162(__float2bfloat16(x), __float2bfloat16(y));
    return *reinterpret_cast<uint32_t*>(&p);
}

// ---------------- setup ----------------
__global__ void __launch_bounds__(256) setup_w(const float* __restrict__ qv) {
    __shared__ float qs[KREF][DDIM];
    __shared__ float G[KREF][KREF];
    __shared__ float cinv[KREF];
    int t = threadIdx.x;
    for (int i = t; i < KREF * DDIM; i += 256) qs[i >> 8][i & 255] = qv[i];
    __syncthreads();
    #pragma unroll
    for (int p = 0; p < 4; p++) {
        int idx = t + p * 256;
        int j = idx >> 5, k = idx & 31;
        float s = 0.f;
        #pragma unroll 8
        for (int d = 0; d < DDIM; d++) s = fmaf(qs[j][d], qs[k][d], s);
        G[j][k] = s;
    }
    __syncthreads();
    if (t < KREF) cinv[t] = 2.0f / G[t][t];
    __syncthreads();
    float w[KREF];
    int d = t;
    #pragma unroll
    for (int k = 0; k < KREF; k++) {
        float acc = qs[k][d];
        #pragma unroll
        for (int j = 0; j < KREF; j++)
            if (j < k) acc = fmaf(-G[j][k], w[j], acc);
        w[k] = cinv[k] * acc;
        g_W[k * DDIM + d] = w[k];
    }
}

__global__ void __launch_bounds__(256) setup_split(const float* __restrict__ qv) {
    int k = blockIdx.x;     // 0..31
    int d = threadIdx.x;    // 0..255
    float w = g_W[k * DDIM + d];
    __nv_bfloat16 wh = __float2bfloat16(w);
    g_Uh[k * DDIM + d] = wh;
    g_Ul[k * DDIM + d] = __float2bfloat16(w - __bfloat162float(wh));
    float q = qv[k * DDIM + d];
    __nv_bfloat16 qh = __float2bfloat16(q);
    g_Qh[d * KREF + k] = qh;
    g_Ql[d * KREF + k] = __float2bfloat16(q - __bfloat162float(qh));
}

// ---------------- SMEM layout (bytes) ----------------
// A tiles: 128 rows x 512B (256 bf16), swizzle chunk^(r&7)
#define SA_H 0
#define SA_L 65536
// B1 (U): 32 rows x 512B, swizzle chunk^(n&7)
#define SB1H 131072
#define SB1L 147456
// B2 (qT): 256 rows x 64B, swizzle chunk^((n>>1)&3)
#define SB2H 163840
#define SB2L 180224
// C: 128 rows x 64B, swizzle chunk^((r>>1)&3)
#define SC_H 196608
#define SC_L 204800
#define SMEM_TOTAL 212992

__global__ void __launch_bounds__(256, 1)
hh_main(const float* __restrict__ in, float* __restrict__ out) {
    extern __shared__ char smem[];
    const uint32_t sb = smem_u32(smem);
    const int tid = threadIdx.x;
    const int wid = tid >> 5, lane = tid & 31;
    const int tile = blockIdx.x;

    const float* Abase = in + (size_t)tile * MT * DDIM;
    float* Obase = out + (size_t)tile * MT * DDIM;

    // ---- stage B1 (U hi/lo): 32x256 bf16 each ----
    #pragma unroll
    for (int i = 0; i < 8; i++) {
        int idx4 = tid + i * 256;            // 2048 groups of 4 elems
        int row = idx4 >> 6;
        int j4 = (idx4 & 63) << 2;
        uint32_t off = row * 512u + ((((uint32_t)(j4 >> 3)) ^ (row & 7)) << 4) + ((j4 & 4) << 1);
        *(uint2*)(smem + SB1H + off) = *(const uint2*)(g_Uh + row * DDIM + j4);
        *(uint2*)(smem + SB1L + off) = *(const uint2*)(g_Ul + row * DDIM + j4);
    }
    // ---- stage B2 (qT hi/lo): 256x32 bf16 each ----
    #pragma unroll
    for (int i = 0; i < 8; i++) {
        int idx4 = tid + i * 256;
        int row = idx4 >> 3;
        int j4 = (idx4 & 7) << 2;
        uint32_t off = row * 64u + ((((uint32_t)(j4 >> 3)) ^ ((row >> 1) & 3)) << 4) + ((j4 & 4) << 1);
        *(uint2*)(smem + SB2H + off) = *(const uint2*)(g_Qh + row * KREF + j4);
        *(uint2*)(smem + SB2L + off) = *(const uint2*)(g_Ql + row * KREF + j4);
    }
    // ---- stage A: load fp32, split bf16 hi/lo ----
    #pragma unroll 4
    for (int i = 0; i < 32; i++) {
        int idx4 = tid + i * 256;            // 8192 float4 groups
        int row = idx4 >> 6;
        int j4 = (idx4 & 63) << 2;
        float4 v = *(const float4*)(Abase + row * DDIM + j4);
        uint32_t h0 = pack_bf16x2(v.x, v.y);
        uint32_t h1 = pack_bf16x2(v.z, v.w);
        __nv_bfloat162 hp0 = *reinterpret_cast<__nv_bfloat162*>(&h0);
        __nv_bfloat162 hp1 = *reinterpret_cast<__nv_bfloat162*>(&h1);
        uint32_t l0 = pack_bf16x2(v.x - __low2float(hp0), v.y - __high2float(hp0));
        uint32_t l1 = pack_bf16x2(v.z - __low2float(hp1), v.w - __high2float(hp1));
        uint32_t off = row * 512u + ((((uint32_t)(j4 >> 3)) ^ (row & 7)) << 4) + ((j4 & 4) << 1);
        uint2 hv; hv.x = h0; hv.y = h1;
        uint2 lv; lv.x = l0; lv.y = l1;
        *(uint2*)(smem + SA_H + off) = hv;
        *(uint2*)(smem + SA_L + off) = lv;
    }
    __syncthreads();

    // ================= GEMM1: C[128x32] = A[128x256] * U^T ==================
    const int m0 = wid * 16;
    {
        float acc[4][4];
        #pragma unroll
        for (int nt = 0; nt < 4; nt++)
            #pragma unroll
            for (int j = 0; j < 4; j++) acc[nt][j] = 0.f;

        #pragma unroll
        for (int ks = 0; ks < 16; ks++) {
            uint32_t ah[4], al[4];
            {
                int r = m0 + (lane & 15);
                uint32_t ch = (uint32_t)(ks * 2 + (lane >> 4));
                uint32_t off = r * 512u + ((ch ^ (r & 7)) << 4);
                ldsm4(ah[0], ah[1], ah[2], ah[3], sb + SA_H + off);
                ldsm4(al[0], al[1], al[2], al[3], sb + SA_L + off);
            }
            uint32_t bh[2][4], bl[2][4];
            #pragma unroll
            for (int t2 = 0; t2 < 2; t2++) {
                int n = t2 * 16 + (lane & 15);
                uint32_t ch = (uint32_t)(ks * 2 + (lane >> 4));
                uint32_t off = n * 512u + ((ch ^ (n & 7)) << 4);
                ldsm4(bh[t2][0], bh[t2][1], bh[t2][2], bh[t2][3], sb + SB1H + off);
                ldsm4(bl[t2][0], bl[t2][1], bl[t2][2], bl[t2][3], sb + SB1L + off);
            }
            #pragma unroll
            for (int nt = 0; nt < 4; nt++) {
                const uint32_t* Bh = bh[nt >> 1];
                const uint32_t* Bl = bl[nt >> 1];
                uint32_t h0 = (nt & 1) ? Bh[1] : Bh[0], h1 = (nt & 1) ? Bh[3] : Bh[2];
                uint32_t q0 = (nt & 1) ? Bl[1] : Bl[0], q1 = (nt & 1) ? Bl[3] : Bl[2];
                mma16816(acc[nt], ah, h0, h1);   // Ah*Uh
                mma16816(acc[nt], ah, q0, q1);   // Ah*Ul
                mma16816(acc[nt], al, h0, h1);   // Al*Uh
            }
        }
        // write C (split hi/lo) to SMEM as GEMM2 A-operand [m][k=32]
        int r1 = m0 + (lane >> 2);
        int cb = (lane & 3) << 2;    // byte offset within 16B chunk (2 bf16 = 4B)
        #pragma unroll
        for (int nt = 0; nt < 4; nt++) {
            #pragma unroll
            for (int h = 0; h < 2; h++) {
                int r = r1 + h * 8;
                float c0 = acc[nt][h * 2 + 0], c1 = acc[nt][h * 2 + 1];
                uint32_t hp = pack_bf16x2(c0, c1);
                __nv_bfloat162 hb = *reinterpret_cast<__nv_bfloat162*>(&hp);
                uint32_t lp = pack_bf16x2(c0 - __low2float(hb), c1 - __high2float(hb));
                uint32_t off = r * 64u + ((((uint32_t)nt) ^ ((r >> 1) & 3)) << 4) + cb;
                *(uint32_t*)(smem + SC_H + off) = hp;
                *(uint32_t*)(smem + SC_L + off) = lp;
            }
        }
    }
    __syncthreads();

    // ========== GEMM2 + epilogue: out = A - C[128x32] * Q^T[32x256] ==========
    #pragma unroll 1
    for (int nc = 0; nc < 8; nc++) {
        float acc[4][4];
        #pragma unroll
        for (int nt = 0; nt < 4; nt++)
            #pragma unroll
            for (int j = 0; j < 4; j++) acc[nt][j] = 0.f;

        #pragma unroll
        for (int ks = 0; ks < 2; ks++) {
            uint32_t chf[4], clf[4];
            {
                int r = m0 + (lane & 15);
                uint32_t ch = (uint32_t)(ks * 2 + (lane >> 4));
                uint32_t off = r * 64u + ((ch ^ ((r >> 1) & 3)) << 4);
                ldsm4(chf[0], chf[1], chf[2], chf[3], sb + SC_H + off);
                ldsm4(clf[0], clf[1], clf[2], clf[3], sb + SC_L + off);
            }
            uint32_t bh[2][4], bl[2][4];
            #pragma unroll
            for (int t2 = 0; t2 < 2; t2++) {
                int n = nc * 32 + t2 * 16 + (lane & 15);
                uint32_t ch = (uint32_t)(ks * 2 + (lane >> 4));
                uint32_t off = n * 64u + ((ch ^ ((n >> 1) & 3)) << 4);
                ldsm4(bh[t2][0], bh[t2][1], bh[t2][2], bh[t2][3], sb + SB2H + off);
                ldsm4(bl[t2][0], bl[t2][1], bl[t2][2], bl[t2][3], sb + SB2L + off);
            }
            #pragma unroll
            for (int nt = 0; nt < 4; nt++) {
                const uint32_t* Bh = bh[nt >> 1];
                const uint32_t* Bl = bl[nt >> 1];
                uint32_t h0 = (nt & 1) ? Bh[1] : Bh[0], h1 = (nt & 1) ? Bh[3] : Bh[2];
                uint32_t q0 = (nt & 1) ? Bl[1] : Bl[0], q1 = (nt & 1) ? Bl[3] : Bl[2];
                mma16816(acc[nt], chf, h0, h1);
                mma16816(acc[nt], chf, q0, q1);
                mma16816(acc[nt], clf, h0, h1);
            }
        }
        // epilogue: out = (Ah + Al) - corr
        int rbase = m0 + (lane >> 2);
        #pragma unroll
        for (int nt = 0; nt < 4; nt++) {
            int col = nc * 32 + nt * 8 + ((lane & 3) << 1);
            #pragma unroll
            for (int h = 0; h < 2; h++) {
                int r = rbase + h * 8;
                uint32_t offA = r * 512u + ((((uint32_t)(col >> 3)) ^ (r & 7)) << 4)
                              + ((col << 1) & 15);
                uint32_t hv = *(const uint32_t*)(smem + SA_H + offA);
                uint32_t lv = *(const uint32_t*)(smem + SA_L + offA);
                __nv_bfloat162 hb = *reinterpret_cast<__nv_bfloat162*>(&hv);
                __nv_bfloat162 lb = *reinterpret_cast<__nv_bfloat162*>(&lv);
                float a0 = __low2float(hb) + __low2float(lb);
                float a1 = __high2float(hb) + __high2float(lb);
                float2 o;
                o.x = a0 - acc[nt][h * 2 + 0];
                o.y = a1 - acc[nt][h * 2 + 1];
                *(float2*)(Obase + (size_t)r * DDIM + col) = o;
            }
        }
    }
}

__global__ void zero_tail_kernel(float* __restrict__ out, long long start, long long end) {
    long long i = start + (long long)blockIdx.x * blockDim.x + threadIdx.x;
    if (i < end) out[i] = 0.0f;
}

extern "C" void kernel_launch(void* const* d_in, const int* in_sizes, int n_in,
                              void* d_out, int out_size) {
    const float* inp = (const float*)d_in[0];   // inputs  [N, 256]
    const float* qv  = (const float*)d_in[1];   // q_vectors [32, 256]
    float* out = (float*)d_out;

    int n_rows = in_sizes[0] / DDIM;
    int n_tiles = n_rows / MT;

    cudaFuncSetAttribute(hh_main, cudaFuncAttributeMaxDynamicSharedMemorySize, SMEM_TOTAL);

    setup_w<<<1, 256>>>(qv);
    setup_split<<<KREF, 256>>>(qv);
    hh_main<<<n_tiles, 256, SMEM_TOTAL>>>(inp, out);

    long long nd = (long long)n_rows * DDIM;
    long long total = (long long)out_size;
    if (total > nd) {
        long long tail = total - nd;
        int zgrid = (int)((tail + 255) / 256);
        zero_tail_kernel<<<zgrid, 256>>>(out, nd, total);
    }
}

// round 5
// speedup vs baseline: 1.6711x; 1.2635x over previous
#include <cuda_runtime.h>
#include <cuda_bf16.h>
#include <cstdint>

#define DDIM 256
#define KREF 32
#define MT   128

// ---------------- device scratch (no allocation) ----------------
__device__ __align__(16) float         g_W[KREF * DDIM];
__device__ __align__(16) __nv_bfloat16 g_Uh[KREF * DDIM];   // [k][d]
__device__ __align__(16) __nv_bfloat16 g_Ul[KREF * DDIM];
__device__ __align__(16) __nv_bfloat16 g_Qh[DDIM * KREF];   // [d][k]
__device__ __align__(16) __nv_bfloat16 g_Ql[DDIM * KREF];

// ---------------- helpers ----------------
__device__ __forceinline__ uint32_t smem_u32(const void* p) {
    uint32_t a;
    asm("{ .reg .u64 t; cvta.to.shared.u64 t, %1; cvt.u32.u64 %0, t; }" : "=r"(a) : "l"(p));
    return a;
}
__device__ __forceinline__ void ldsm4(uint32_t& r0, uint32_t& r1, uint32_t& r2, uint32_t& r3,
                                      uint32_t addr) {
    asm volatile("ldmatrix.sync.aligned.m8n8.x4.shared.b16 {%0,%1,%2,%3}, [%4];"
                 : "=r"(r0), "=r"(r1), "=r"(r2), "=r"(r3) : "r"(addr));
}
__device__ __forceinline__ void mma16816(float* d, const uint32_t* a, uint32_t b0, uint32_t b1) {
    asm volatile(
        "mma.sync.aligned.m16n8k16.row.col.f32.bf16.bf16.f32 "
        "{%0,%1,%2,%3},{%4,%5,%6,%7},{%8,%9},{%0,%1,%2,%3};"
        : "+f"(d[0]), "+f"(d[1]), "+f"(d[2]), "+f"(d[3])
        : "r"(a[0]), "r"(a[1]), "r"(a[2]), "r"(a[3]), "r"(b0), "r"(b1));
}
__device__ __forceinline__ uint32_t pack_bf16x2(float x, float y) {
    __nv_bfloat162 p = __halves2bfloat162(__float2bfloat16(x), __float2bfloat16(y));
    return *reinterpret_cast<uint32_t*>(&p);
}
// split a float2 into hi bf16x2 and lo (residual) bf16x2
__device__ __forceinline__ void split2(float2 v, uint32_t& hi, uint32_t& lo) {
    hi = pack_bf16x2(v.x, v.y);
    __nv_bfloat162 hb = *reinterpret_cast<__nv_bfloat162*>(&hi);
    lo = pack_bf16x2(v.x - __low2float(hb), v.y - __high2float(hb));
}

// ---------------- setup ----------------
__global__ void __launch_bounds__(256) setup_w(const float* __restrict__ qv) {
    __shared__ float qs[KREF][DDIM];
    __shared__ float G[KREF][KREF];
    __shared__ float cinv[KREF];
    int t = threadIdx.x;
    for (int i = t; i < KREF * DDIM; i += 256) qs[i >> 8][i & 255] = qv[i];
    __syncthreads();
    #pragma unroll
    for (int p = 0; p < 4; p++) {
        int idx = t + p * 256;
        int j = idx >> 5, k = idx & 31;
        float s = 0.f;
        #pragma unroll 8
        for (int d = 0; d < DDIM; d++) s = fmaf(qs[j][d], qs[k][d], s);
        G[j][k] = s;
    }
    __syncthreads();
    if (t < KREF) cinv[t] = 2.0f / G[t][t];
    __syncthreads();
    float w[KREF];
    int d = t;
    #pragma unroll
    for (int k = 0; k < KREF; k++) {
        float acc = qs[k][d];
        #pragma unroll
        for (int j = 0; j < KREF; j++)
            if (j < k) acc = fmaf(-G[j][k], w[j], acc);
        w[k] = cinv[k] * acc;
        g_W[k * DDIM + d] = w[k];
    }
}

__global__ void __launch_bounds__(256) setup_split(const float* __restrict__ qv) {
    int k = blockIdx.x;
    int d = threadIdx.x;
    float w = g_W[k * DDIM + d];
    __nv_bfloat16 wh = __float2bfloat16(w);
    g_Uh[k * DDIM + d] = wh;
    g_Ul[k * DDIM + d] = __float2bfloat16(w - __bfloat162float(wh));
    float q = qv[k * DDIM + d];
    __nv_bfloat16 qh = __float2bfloat16(q);
    g_Qh[d * KREF + k] = qh;
    g_Ql[d * KREF + k] = __float2bfloat16(q - __bfloat162float(qh));
}

// ---------------- SMEM layout (bytes) ----------------
// B1 (U): 32 rows x 512B, swizzle chunk^(n&7)
#define SB1H 0
#define SB1L 16384
// B2 (qT): 256 rows x 64B, swizzle chunk^((n>>1)&3)
#define SB2H 32768
#define SB2L 49152
#define SMEM_TOTAL 65536

__global__ void __launch_bounds__(256)
hh_main(const float* __restrict__ in, float* __restrict__ out) {
    extern __shared__ char smem[];
    const uint32_t sb = smem_u32(smem);
    const int tid = threadIdx.x;
    const int wid = tid >> 5, lane = tid & 31;
    const int tile = blockIdx.x;

    const float* Abase = in + (size_t)tile * MT * DDIM;
    float* Obase = out + (size_t)tile * MT * DDIM;

    // ---- stage B1 (U hi/lo): 32x256 bf16 each ----
    #pragma unroll
    for (int i = 0; i < 8; i++) {
        int idx4 = tid + i * 256;
        int row = idx4 >> 6;
        int j4 = (idx4 & 63) << 2;
        uint32_t off = row * 512u + ((((uint32_t)(j4 >> 3)) ^ (row & 7)) << 4) + ((j4 & 4) << 1);
        *(uint2*)(smem + SB1H + off) = *(const uint2*)(g_Uh + row * DDIM + j4);
        *(uint2*)(smem + SB1L + off) = *(const uint2*)(g_Ul + row * DDIM + j4);
    }
    // ---- stage B2 (qT hi/lo): 256x32 bf16 each ----
    #pragma unroll
    for (int i = 0; i < 8; i++) {
        int idx4 = tid + i * 256;
        int row = idx4 >> 3;
        int j4 = (idx4 & 7) << 2;
        uint32_t off = row * 64u + ((((uint32_t)(j4 >> 3)) ^ ((row >> 1) & 3)) << 4) + ((j4 & 4) << 1);
        *(uint2*)(smem + SB2H + off) = *(const uint2*)(g_Qh + row * KREF + j4);
        *(uint2*)(smem + SB2L + off) = *(const uint2*)(g_Ql + row * KREF + j4);
    }
    __syncthreads();

    // ================= GEMM1: C[128x32] = A * U^T (A frags via LDG) ==========
    const int m0 = wid * 16;
    const int r0 = m0 + (lane >> 2);
    const float* Afrag = Abase + (size_t)r0 * DDIM + ((lane & 3) << 1);

    float accC[4][4];
    #pragma unroll
    for (int nt = 0; nt < 4; nt++)
        #pragma unroll
        for (int j = 0; j < 4; j++) accC[nt][j] = 0.f;

    float2 p0 = *(const float2*)(Afrag);
    float2 p1 = *(const float2*)(Afrag + 8 * DDIM);
    float2 p2 = *(const float2*)(Afrag + 8);
    float2 p3 = *(const float2*)(Afrag + 8 * DDIM + 8);

    #pragma unroll
    for (int ks = 0; ks < 16; ks++) {
        float2 c0 = p0, c1 = p1, c2 = p2, c3 = p3;
        if (ks < 15) {
            const float* nx = Afrag + (ks + 1) * 16;
            p0 = *(const float2*)(nx);
            p1 = *(const float2*)(nx + 8 * DDIM);
            p2 = *(const float2*)(nx + 8);
            p3 = *(const float2*)(nx + 8 * DDIM + 8);
        }
        uint32_t ah[4], al[4];
        split2(c0, ah[0], al[0]);
        split2(c1, ah[1], al[1]);
        split2(c2, ah[2], al[2]);
        split2(c3, ah[3], al[3]);

        uint32_t bh[2][4], bl[2][4];
        #pragma unroll
        for (int t2 = 0; t2 < 2; t2++) {
            int n = t2 * 16 + (lane & 15);
            uint32_t ch = (uint32_t)(ks * 2 + (lane >> 4));
            uint32_t off = n * 512u + ((ch ^ (n & 7)) << 4);
            ldsm4(bh[t2][0], bh[t2][1], bh[t2][2], bh[t2][3], sb + SB1H + off);
            ldsm4(bl[t2][0], bl[t2][1], bl[t2][2], bl[t2][3], sb + SB1L + off);
        }
        #pragma unroll
        for (int nt = 0; nt < 4; nt++) {
            const uint32_t* Bh = bh[nt >> 1];
            const uint32_t* Bl = bl[nt >> 1];
            uint32_t h0 = (nt & 1) ? Bh[1] : Bh[0], h1 = (nt & 1) ? Bh[3] : Bh[2];
            uint32_t q0 = (nt & 1) ? Bl[1] : Bl[0], q1 = (nt & 1) ? Bl[3] : Bl[2];
            mma16816(accC[nt], ah, h0, h1);
            mma16816(accC[nt], ah, q0, q1);
            mma16816(accC[nt], al, h0, h1);
        }
    }

    // ---- repack C (acc layout == GEMM2 A-fragment layout, k = n) ----
    uint32_t ch[2][4], cl[2][4];
    #pragma unroll
    for (int kb = 0; kb < 2; kb++) {
        float2 v;
        v.x = accC[kb * 2][0];     v.y = accC[kb * 2][1];     split2(v, ch[kb][0], cl[kb][0]);
        v.x = accC[kb * 2][2];     v.y = accC[kb * 2][3];     split2(v, ch[kb][1], cl[kb][1]);
        v.x = accC[kb * 2 + 1][0]; v.y = accC[kb * 2 + 1][1]; split2(v, ch[kb][2], cl[kb][2]);
        v.x = accC[kb * 2 + 1][2]; v.y = accC[kb * 2 + 1][3]; split2(v, ch[kb][3], cl[kb][3]);
    }

    // ========== GEMM2 + epilogue: out = A - C * Q^T, streamed over 16-col tiles ==========
    #pragma unroll 2
    for (int nc16 = 0; nc16 < 16; nc16++) {
        float acc[2][4];
        #pragma unroll
        for (int nt = 0; nt < 2; nt++)
            #pragma unroll
            for (int j = 0; j < 4; j++) acc[nt][j] = 0.f;

        #pragma unroll
        for (int kb = 0; kb < 2; kb++) {
            uint32_t bh[4], bl[4];
            int n = nc16 * 16 + (lane & 15);
            uint32_t chn = (uint32_t)(kb * 2 + (lane >> 4));
            uint32_t off = n * 64u + ((chn ^ ((n >> 1) & 3)) << 4);
            ldsm4(bh[0], bh[1], bh[2], bh[3], sb + SB2H + off);
            ldsm4(bl[0], bl[1], bl[2], bl[3], sb + SB2L + off);
            #pragma unroll
            for (int nt = 0; nt < 2; nt++) {
                uint32_t h0 = nt ? bh[1] : bh[0], h1 = nt ? bh[3] : bh[2];
                uint32_t q0 = nt ? bl[1] : bl[0], q1 = nt ? bl[3] : bl[2];
                mma16816(acc[nt], ch[kb], h0, h1);
                mma16816(acc[nt], ch[kb], q0, q1);
                mma16816(acc[nt], cl[kb], h0, h1);
            }
        }
        // epilogue: re-read A fp32 (L2-hot), subtract, store
        #pragma unroll
        for (int nt = 0; nt < 2; nt++) {
            int col = nc16 * 16 + nt * 8 + ((lane & 3) << 1);
            #pragma unroll
            for (int h = 0; h < 2; h++) {
                int r = r0 + h * 8;
                const float* ap = Abase + (size_t)r * DDIM + col;
                float2 av = *(const float2*)ap;
                float2 o;
                o.x = av.x - acc[nt][h * 2 + 0];
                o.y = av.y - acc[nt][h * 2 + 1];
                *(float2*)(Obase + (size_t)r * DDIM + col) = o;
            }
        }
    }
}

__global__ void zero_tail_kernel(float* __restrict__ out, long long start, long long end) {
    long long i = start + (long long)blockIdx.x * blockDim.x + threadIdx.x;
    if (i < end) out[i] = 0.0f;
}

extern "C" void kernel_launch(void* const* d_in, const int* in_sizes, int n_in,
                              void* d_out, int out_size) {
    const float* inp = (const float*)d_in[0];   // inputs  [N, 256]
    const float* qv  = (const float*)d_in[1];   // q_vectors [32, 256]
    float* out = (float*)d_out;

    int n_rows = in_sizes[0] / DDIM;
    int n_tiles = n_rows / MT;

    cudaFuncSetAttribute(hh_main, cudaFuncAttributeMaxDynamicSharedMemorySize, SMEM_TOTAL);

    setup_w<<<1, 256>>>(qv);
    setup_split<<<KREF, 256>>>(qv);
    hh_main<<<n_tiles, 256, SMEM_TOTAL>>>(inp, out);

    long long nd = (long long)n_rows * DDIM;
    long long total = (long long)out_size;
    if (total > nd) {
        long long tail = total - nd;
        int zgrid = (int)((tail + 255) / 256);
        zero_tail_kernel<<<zgrid, 256>>>(out, nd, total);
    }
}

// round 6
// speedup vs baseline: 1.7910x; 1.0717x over previous
#include <cuda_runtime.h>
#include <cuda_bf16.h>
#include <cstdint>

#define DDIM 256
#define KREF 32
#define MT   128

// ---------------- device scratch (no allocation) ----------------
__device__ __align__(16) __nv_bfloat16 g_Uh[KREF * DDIM];   // [k][d]
__device__ __align__(16) __nv_bfloat16 g_Ul[KREF * DDIM];
__device__ __align__(16) __nv_bfloat16 g_Qh[DDIM * KREF];   // [d][k]
__device__ __align__(16) __nv_bfloat16 g_Ql[DDIM * KREF];

// ---------------- helpers ----------------
__device__ __forceinline__ uint32_t smem_u32(const void* p) {
    uint32_t a;
    asm("{ .reg .u64 t; cvta.to.shared.u64 t, %1; cvt.u32.u64 %0, t; }" : "=r"(a) : "l"(p));
    return a;
}
__device__ __forceinline__ void ldsm4(uint32_t& r0, uint32_t& r1, uint32_t& r2, uint32_t& r3,
                                      uint32_t addr) {
    asm volatile("ldmatrix.sync.aligned.m8n8.x4.shared.b16 {%0,%1,%2,%3}, [%4];"
                 : "=r"(r0), "=r"(r1), "=r"(r2), "=r"(r3) : "r"(addr));
}
__device__ __forceinline__ void mma16816(float* d, const uint32_t* a, uint32_t b0, uint32_t b1) {
    asm volatile(
        "mma.sync.aligned.m16n8k16.row.col.f32.bf16.bf16.f32 "
        "{%0,%1,%2,%3},{%4,%5,%6,%7},{%8,%9},{%0,%1,%2,%3};"
        : "+f"(d[0]), "+f"(d[1]), "+f"(d[2]), "+f"(d[3])
        : "r"(a[0]), "r"(a[1]), "r"(a[2]), "r"(a[3]), "r"(b0), "r"(b1));
}
__device__ __forceinline__ uint32_t pack_bf16x2(float x, float y) {
    __nv_bfloat162 p = __halves2bfloat162(__float2bfloat16(x), __float2bfloat16(y));
    return *reinterpret_cast<uint32_t*>(&p);
}
__device__ __forceinline__ void split2(float2 v, uint32_t& hi, uint32_t& lo) {
    hi = pack_bf16x2(v.x, v.y);
    __nv_bfloat162 hb = *reinterpret_cast<__nv_bfloat162*>(&hi);
    lo = pack_bf16x2(v.x - __low2float(hb), v.y - __high2float(hb));
}

// ---------------- setup (single kernel, W stays in registers) ----------------
__global__ void __launch_bounds__(256) setup_all(const float* __restrict__ qv) {
    __shared__ float qs[KREF][DDIM];
    __shared__ float G[KREF][KREF];
    __shared__ float cinv[KREF];
    int t = threadIdx.x;
    for (int i = t; i < KREF * DDIM; i += 256) qs[i >> 8][i & 255] = qv[i];
    __syncthreads();
    #pragma unroll
    for (int p = 0; p < 4; p++) {
        int idx = t + p * 256;
        int j = idx >> 5, k = idx & 31;
        float s = 0.f;
        #pragma unroll 8
        for (int d = 0; d < DDIM; d++) s = fmaf(qs[j][d], qs[k][d], s);
        G[j][k] = s;
    }
    __syncthreads();
    if (t < KREF) cinv[t] = 2.0f / G[t][t];
    __syncthreads();

    float w[KREF];
    const int d = t;
    #pragma unroll
    for (int k = 0; k < KREF; k++) {
        float acc = qs[k][d];
        #pragma unroll
        for (int j = 0; j < KREF; j++)
            if (j < k) acc = fmaf(-G[j][k], w[j], acc);
        w[k] = cinv[k] * acc;
    }
    // splits (same thread owns dimension d for every k)
    #pragma unroll
    for (int k = 0; k < KREF; k++) {
        float wv = w[k];
        __nv_bfloat16 wh = __float2bfloat16(wv);
        g_Uh[k * DDIM + d] = wh;
        g_Ul[k * DDIM + d] = __float2bfloat16(wv - __bfloat162float(wh));
        float q = qs[k][d];
        __nv_bfloat16 qh = __float2bfloat16(q);
        g_Qh[d * KREF + k] = qh;
        g_Ql[d * KREF + k] = __float2bfloat16(q - __bfloat162float(qh));
    }
}

// ---------------- SMEM layout (bytes) ----------------
#define SB1H 0
#define SB1L 16384
#define SB2H 32768
#define SB2L 49152
#define SMEM_TOTAL 65536

__global__ void __launch_bounds__(256, 2)
hh_main(const float* __restrict__ in, float* __restrict__ out,
        long long nd, long long total) {
    extern __shared__ char smem[];
    const uint32_t sb = smem_u32(smem);
    const int tid = threadIdx.x;
    const int wid = tid >> 5, lane = tid & 31;
    const int tile = blockIdx.x;

    const float* Abase = in + (size_t)tile * MT * DDIM;
    float* Obase = out + (size_t)tile * MT * DDIM;

    // ---- zero my slice of the tail (logabsdet) ----
    {
        long long tail = total - nd;
        int ntile = (int)gridDim.x;
        long long per = (tail + ntile - 1) / ntile;
        long long start = nd + (long long)tile * per;
        for (long long j = tid; j < per; j += 256) {
            long long idx = start + j;
            if (idx < total) out[idx] = 0.0f;
        }
    }

    // ---- stage B1 (U hi/lo): 32x256 bf16 each ----
    #pragma unroll
    for (int i = 0; i < 8; i++) {
        int idx4 = tid + i * 256;
        int row = idx4 >> 6;
        int j4 = (idx4 & 63) << 2;
        uint32_t off = row * 512u + ((((uint32_t)(j4 >> 3)) ^ (row & 7)) << 4) + ((j4 & 4) << 1);
        *(uint2*)(smem + SB1H + off) = *(const uint2*)(g_Uh + row * DDIM + j4);
        *(uint2*)(smem + SB1L + off) = *(const uint2*)(g_Ul + row * DDIM + j4);
    }
    // ---- stage B2 (qT hi/lo): 256x32 bf16 each ----
    #pragma unroll
    for (int i = 0; i < 8; i++) {
        int idx4 = tid + i * 256;
        int row = idx4 >> 3;
        int j4 = (idx4 & 7) << 2;
        uint32_t off = row * 64u + ((((uint32_t)(j4 >> 3)) ^ ((row >> 1) & 3)) << 4) + ((j4 & 4) << 1);
        *(uint2*)(smem + SB2H + off) = *(const uint2*)(g_Qh + row * KREF + j4);
        *(uint2*)(smem + SB2L + off) = *(const uint2*)(g_Ql + row * KREF + j4);
    }
    __syncthreads();

    // ================= GEMM1: C[128x32] = A * U^T (A frags via LDG) ==========
    const int m0 = wid * 16;
    const int r0 = m0 + (lane >> 2);
    const float* Afrag = Abase + (size_t)r0 * DDIM + ((lane & 3) << 1);

    float accC[4][4];
    #pragma unroll
    for (int nt = 0; nt < 4; nt++)
        #pragma unroll
        for (int j = 0; j < 4; j++) accC[nt][j] = 0.f;

    float2 p0 = *(const float2*)(Afrag);
    float2 p1 = *(const float2*)(Afrag + 8 * DDIM);
    float2 p2 = *(const float2*)(Afrag + 8);
    float2 p3 = *(const float2*)(Afrag + 8 * DDIM + 8);

    #pragma unroll
    for (int ks = 0; ks < 16; ks++) {
        float2 c0 = p0, c1 = p1, c2 = p2, c3 = p3;
        if (ks < 15) {
            const float* nx = Afrag + (ks + 1) * 16;
            p0 = *(const float2*)(nx);
            p1 = *(const float2*)(nx + 8 * DDIM);
            p2 = *(const float2*)(nx + 8);
            p3 = *(const float2*)(nx + 8 * DDIM + 8);
        }
        uint32_t ah[4], al[4];
        split2(c0, ah[0], al[0]);
        split2(c1, ah[1], al[1]);
        split2(c2, ah[2], al[2]);
        split2(c3, ah[3], al[3]);

        uint32_t bh[2][4], bl[2][4];
        #pragma unroll
        for (int t2 = 0; t2 < 2; t2++) {
            int n = t2 * 16 + (lane & 15);
            uint32_t ch = (uint32_t)(ks * 2 + (lane >> 4));
            uint32_t off = n * 512u + ((ch ^ (n & 7)) << 4);
            ldsm4(bh[t2][0], bh[t2][1], bh[t2][2], bh[t2][3], sb + SB1H + off);
            ldsm4(bl[t2][0], bl[t2][1], bl[t2][2], bl[t2][3], sb + SB1L + off);
        }
        #pragma unroll
        for (int nt = 0; nt < 4; nt++) {
            const uint32_t* Bh = bh[nt >> 1];
            const uint32_t* Bl = bl[nt >> 1];
            uint32_t h0 = (nt & 1) ? Bh[1] : Bh[0], h1 = (nt & 1) ? Bh[3] : Bh[2];
            uint32_t q0 = (nt & 1) ? Bl[1] : Bl[0], q1 = (nt & 1) ? Bl[3] : Bl[2];
            mma16816(accC[nt], ah, h0, h1);
            mma16816(accC[nt], ah, q0, q1);
            mma16816(accC[nt], al, h0, h1);
        }
    }

    // ---- repack C (acc layout == GEMM2 A-fragment layout, k = n) ----
    uint32_t ch[2][4], cl[2][4];
    #pragma unroll
    for (int kb = 0; kb < 2; kb++) {
        float2 v;
        v.x = accC[kb * 2][0];     v.y = accC[kb * 2][1];     split2(v, ch[kb][0], cl[kb][0]);
        v.x = accC[kb * 2][2];     v.y = accC[kb * 2][3];     split2(v, ch[kb][1], cl[kb][1]);
        v.x = accC[kb * 2 + 1][0]; v.y = accC[kb * 2 + 1][1]; split2(v, ch[kb][2], cl[kb][2]);
        v.x = accC[kb * 2 + 1][2]; v.y = accC[kb * 2 + 1][3]; split2(v, ch[kb][3], cl[kb][3]);
    }

    // ========== GEMM2 + epilogue: out = A - C * Q^T, streamed over 16-col tiles ==========
    #pragma unroll 2
    for (int nc16 = 0; nc16 < 16; nc16++) {
        float acc[2][4];
        #pragma unroll
        for (int nt = 0; nt < 2; nt++)
            #pragma unroll
            for (int j = 0; j < 4; j++) acc[nt][j] = 0.f;

        #pragma unroll
        for (int kb = 0; kb < 2; kb++) {
            uint32_t bh[4], bl[4];
            int n = nc16 * 16 + (lane & 15);
            uint32_t chn = (uint32_t)(kb * 2 + (lane >> 4));
            uint32_t off = n * 64u + ((chn ^ ((n >> 1) & 3)) << 4);
            ldsm4(bh[0], bh[1], bh[2], bh[3], sb + SB2H + off);
            ldsm4(bl[0], bl[1], bl[2], bl[3], sb + SB2L + off);
            #pragma unroll
            for (int nt = 0; nt < 2; nt++) {
                uint32_t h0 = nt ? bh[1] : bh[0], h1 = nt ? bh[3] : bh[2];
                uint32_t q0 = nt ? bl[1] : bl[0], q1 = nt ? bl[3] : bl[2];
                mma16816(acc[nt], ch[kb], h0, h1);
                mma16816(acc[nt], ch[kb], q0, q1);
                mma16816(acc[nt], cl[kb], h0, h1);
            }
        }
        // epilogue: re-read A fp32 (L2-hot), subtract, store
        #pragma unroll
        for (int nt = 0; nt < 2; nt++) {
            int col = nc16 * 16 + nt * 8 + ((lane & 3) << 1);
            #pragma unroll
            for (int h = 0; h < 2; h++) {
                int r = r0 + h * 8;
                const float* ap = Abase + (size_t)r * DDIM + col;
                float2 av = *(const float2*)ap;
                float2 o;
                o.x = av.x - acc[nt][h * 2 + 0];
                o.y = av.y - acc[nt][h * 2 + 1];
                *(float2*)(Obase + (size_t)r * DDIM + col) = o;
            }
        }
    }
}

extern "C" void kernel_launch(void* const* d_in, const int* in_sizes, int n_in,
                              void* d_out, int out_size) {
    const float* inp = (const float*)d_in[0];   // inputs  [N, 256]
    const float* qv  = (const float*)d_in[1];   // q_vectors [32, 256]
    float* out = (float*)d_out;

    int n_rows = in_sizes[0] / DDIM;
    int n_tiles = n_rows / MT;

    cudaFuncSetAttribute(hh_main, cudaFuncAttributeMaxDynamicSharedMemorySize, SMEM_TOTAL);

    long long nd = (long long)n_rows * DDIM;
    long long total = (long long)out_size;

    setup_all<<<1, 256>>>(qv);
    hh_main<<<n_tiles, 256, SMEM_TOTAL>>>(inp, out, nd, total);
}

// round 7
// speedup vs baseline: 1.8150x; 1.0134x over previous
#include <cuda_runtime.h>
#include <cuda_bf16.h>
#include <cstdint>

#define DDIM 256
#define KREF 32
#define MT   256    // rows per CTA (8 warps x m32)

// ---------------- device scratch (no allocation) ----------------
__device__ __align__(16) __nv_bfloat16 g_Uh[KREF * DDIM];   // [k][d]
__device__ __align__(16) __nv_bfloat16 g_Ul[KREF * DDIM];
__device__ __align__(16) __nv_bfloat16 g_Qh[DDIM * KREF];   // [d][k]
__device__ __align__(16) __nv_bfloat16 g_Ql[DDIM * KREF];

// ---------------- helpers ----------------
__device__ __forceinline__ uint32_t smem_u32(const void* p) {
    uint32_t a;
    asm("{ .reg .u64 t; cvta.to.shared.u64 t, %1; cvt.u32.u64 %0, t; }" : "=r"(a) : "l"(p));
    return a;
}
__device__ __forceinline__ void ldsm4(uint32_t& r0, uint32_t& r1, uint32_t& r2, uint32_t& r3,
                                      uint32_t addr) {
    asm volatile("ldmatrix.sync.aligned.m8n8.x4.shared.b16 {%0,%1,%2,%3}, [%4];"
                 : "=r"(r0), "=r"(r1), "=r"(r2), "=r"(r3) : "r"(addr));
}
__device__ __forceinline__ void mma16816(float* d, const uint32_t* a, uint32_t b0, uint32_t b1) {
    asm volatile(
        "mma.sync.aligned.m16n8k16.row.col.f32.bf16.bf16.f32 "
        "{%0,%1,%2,%3},{%4,%5,%6,%7},{%8,%9},{%0,%1,%2,%3};"
        : "+f"(d[0]), "+f"(d[1]), "+f"(d[2]), "+f"(d[3])
        : "r"(a[0]), "r"(a[1]), "r"(a[2]), "r"(a[3]), "r"(b0), "r"(b1));
}
__device__ __forceinline__ uint32_t pack_bf16x2(float x, float y) {
    __nv_bfloat162 p = __halves2bfloat162(__float2bfloat16(x), __float2bfloat16(y));
    return *reinterpret_cast<uint32_t*>(&p);
}
__device__ __forceinline__ void split2(float2 v, uint32_t& hi, uint32_t& lo) {
    hi = pack_bf16x2(v.x, v.y);
    __nv_bfloat162 hb = *reinterpret_cast<__nv_bfloat162*>(&hi);
    lo = pack_bf16x2(v.x - __low2float(hb), v.y - __high2float(hb));
}

// ---------------- setup (single kernel, W stays in registers) ----------------
__global__ void __launch_bounds__(256) setup_all(const float* __restrict__ qv) {
    __shared__ float qs[KREF][DDIM];
    __shared__ float G[KREF][KREF];
    __shared__ float cinv[KREF];
    int t = threadIdx.x;
    for (int i = t; i < KREF * DDIM; i += 256) qs[i >> 8][i & 255] = qv[i];
    __syncthreads();
    #pragma unroll
    for (int p = 0; p < 4; p++) {
        int idx = t + p * 256;
        int j = idx >> 5, k = idx & 31;
        float s = 0.f;
        #pragma unroll 8
        for (int d = 0; d < DDIM; d++) s = fmaf(qs[j][d], qs[k][d], s);
        G[j][k] = s;
    }
    __syncthreads();
    if (t < KREF) cinv[t] = 2.0f / G[t][t];
    __syncthreads();

    float w[KREF];
    const int d = t;
    #pragma unroll
    for (int k = 0; k < KREF; k++) {
        float acc = qs[k][d];
        #pragma unroll
        for (int j = 0; j < KREF; j++)
            if (j < k) acc = fmaf(-G[j][k], w[j], acc);
        w[k] = cinv[k] * acc;
    }
    #pragma unroll
    for (int k = 0; k < KREF; k++) {
        float wv = w[k];
        __nv_bfloat16 wh = __float2bfloat16(wv);
        g_Uh[k * DDIM + d] = wh;
        g_Ul[k * DDIM + d] = __float2bfloat16(wv - __bfloat162float(wh));
        float q = qs[k][d];
        __nv_bfloat16 qh = __float2bfloat16(q);
        g_Qh[d * KREF + k] = qh;
        g_Ql[d * KREF + k] = __float2bfloat16(q - __bfloat162float(qh));
    }
}

// ---------------- SMEM layout (bytes) ----------------
#define SB1H 0
#define SB1L 16384
#define SB2H 32768
#define SB2L 49152
#define SMEM_TOTAL 65536

__global__ void __launch_bounds__(256, 2)
hh_main(const float* __restrict__ in, float* __restrict__ out,
        long long nd, long long total) {
    extern __shared__ char smem[];
    const uint32_t sb = smem_u32(smem);
    const int tid = threadIdx.x;
    const int wid = tid >> 5, lane = tid & 31;
    const int tile = blockIdx.x;

    const float* Abase = in + (size_t)tile * MT * DDIM;
    float* Obase = out + (size_t)tile * MT * DDIM;

    // ---- zero my slice of the tail (logabsdet) ----
    {
        long long tail = total - nd;
        int ntile = (int)gridDim.x;
        long long per = (tail + ntile - 1) / ntile;
        long long start = nd + (long long)tile * per;
        for (long long j = tid; j < per; j += 256) {
            long long idx = start + j;
            if (idx < total) out[idx] = 0.0f;
        }
    }

    // ---- stage B1 (U hi/lo): 32x256 bf16 each ----
    #pragma unroll
    for (int i = 0; i < 8; i++) {
        int idx4 = tid + i * 256;
        int row = idx4 >> 6;
        int j4 = (idx4 & 63) << 2;
        uint32_t off = row * 512u + ((((uint32_t)(j4 >> 3)) ^ (row & 7)) << 4) + ((j4 & 4) << 1);
        *(uint2*)(smem + SB1H + off) = *(const uint2*)(g_Uh + row * DDIM + j4);
        *(uint2*)(smem + SB1L + off) = *(const uint2*)(g_Ul + row * DDIM + j4);
    }
    // ---- stage B2 (qT hi/lo): 256x32 bf16 each ----
    #pragma unroll
    for (int i = 0; i < 8; i++) {
        int idx4 = tid + i * 256;
        int row = idx4 >> 3;
        int j4 = (idx4 & 7) << 2;
        uint32_t off = row * 64u + ((((uint32_t)(j4 >> 3)) ^ ((row >> 1) & 3)) << 4) + ((j4 & 4) << 1);
        *(uint2*)(smem + SB2H + off) = *(const uint2*)(g_Qh + row * KREF + j4);
        *(uint2*)(smem + SB2L + off) = *(const uint2*)(g_Ql + row * KREF + j4);
    }
    __syncthreads();

    // ========== GEMM1: C[256x32] = A * U^T, each warp m32 (2 m16 blocks) ==========
    const int mrow = wid * 32;
    const int rl = lane >> 2;
    const float* Af[2];
    Af[0] = Abase + (size_t)(mrow + rl) * DDIM + ((lane & 3) << 1);
    Af[1] = Af[0] + 16 * DDIM;

    float accC[2][4][4];
    #pragma unroll
    for (int mb = 0; mb < 2; mb++)
        #pragma unroll
        for (int nt = 0; nt < 4; nt++)
            #pragma unroll
            for (int j = 0; j < 4; j++) accC[mb][nt][j] = 0.f;

    float2 pf[2][4];
    #pragma unroll
    for (int mb = 0; mb < 2; mb++) {
        pf[mb][0] = *(const float2*)(Af[mb]);
        pf[mb][1] = *(const float2*)(Af[mb] + 8 * DDIM);
        pf[mb][2] = *(const float2*)(Af[mb] + 8);
        pf[mb][3] = *(const float2*)(Af[mb] + 8 * DDIM + 8);
    }

    #pragma unroll
    for (int ks = 0; ks < 16; ks++) {
        uint32_t ah[2][4], al[2][4];
        #pragma unroll
        for (int mb = 0; mb < 2; mb++) {
            #pragma unroll
            for (int j = 0; j < 4; j++) split2(pf[mb][j], ah[mb][j], al[mb][j]);
        }
        if (ks < 15) {
            #pragma unroll
            for (int mb = 0; mb < 2; mb++) {
                const float* nx = Af[mb] + (ks + 1) * 16;
                pf[mb][0] = *(const float2*)(nx);
                pf[mb][1] = *(const float2*)(nx + 8 * DDIM);
                pf[mb][2] = *(const float2*)(nx + 8);
                pf[mb][3] = *(const float2*)(nx + 8 * DDIM + 8);
            }
        }

        uint32_t bh[2][4], bl[2][4];
        #pragma unroll
        for (int t2 = 0; t2 < 2; t2++) {
            int n = t2 * 16 + (lane & 15);
            uint32_t ch = (uint32_t)(ks * 2 + (lane >> 4));
            uint32_t off = n * 512u + ((ch ^ (n & 7)) << 4);
            ldsm4(bh[t2][0], bh[t2][1], bh[t2][2], bh[t2][3], sb + SB1H + off);
            ldsm4(bl[t2][0], bl[t2][1], bl[t2][2], bl[t2][3], sb + SB1L + off);
        }
        #pragma unroll
        for (int mb = 0; mb < 2; mb++) {
            #pragma unroll
            for (int nt = 0; nt < 4; nt++) {
                const uint32_t* Bh = bh[nt >> 1];
                const uint32_t* Bl = bl[nt >> 1];
                uint32_t h0 = (nt & 1) ? Bh[1] : Bh[0], h1 = (nt & 1) ? Bh[3] : Bh[2];
                uint32_t q0 = (nt & 1) ? Bl[1] : Bl[0], q1 = (nt & 1) ? Bl[3] : Bl[2];
                mma16816(accC[mb][nt], ah[mb], h0, h1);
                mma16816(accC[mb][nt], ah[mb], q0, q1);
                mma16816(accC[mb][nt], al[mb], h0, h1);
            }
        }
    }

    // ---- repack C (acc layout == GEMM2 A-fragment layout, k = n) ----
    uint32_t ch[2][2][4], cl[2][2][4];
    #pragma unroll
    for (int mb = 0; mb < 2; mb++) {
        #pragma unroll
        for (int kb = 0; kb < 2; kb++) {
            float2 v;
            v.x = accC[mb][kb * 2][0];     v.y = accC[mb][kb * 2][1];     split2(v, ch[mb][kb][0], cl[mb][kb][0]);
            v.x = accC[mb][kb * 2][2];     v.y = accC[mb][kb * 2][3];     split2(v, ch[mb][kb][1], cl[mb][kb][1]);
            v.x = accC[mb][kb * 2 + 1][0]; v.y = accC[mb][kb * 2 + 1][1]; split2(v, ch[mb][kb][2], cl[mb][kb][2]);
            v.x = accC[mb][kb * 2 + 1][2]; v.y = accC[mb][kb * 2 + 1][3]; split2(v, ch[mb][kb][3], cl[mb][kb][3]);
        }
    }

    // ========== GEMM2 + epilogue: out = A - C * Q^T ==========
    #pragma unroll 1
    for (int nc16 = 0; nc16 < 16; nc16++) {
        float acc[2][2][4];
        #pragma unroll
        for (int mb = 0; mb < 2; mb++)
            #pragma unroll
            for (int nt = 0; nt < 2; nt++)
                #pragma unroll
                for (int j = 0; j < 4; j++) acc[mb][nt][j] = 0.f;

        #pragma unroll
        for (int kb = 0; kb < 2; kb++) {
            uint32_t bh[4], bl[4];
            int n = nc16 * 16 + (lane & 15);
            uint32_t chn = (uint32_t)(kb * 2 + (lane >> 4));
            uint32_t off = n * 64u + ((chn ^ ((n >> 1) & 3)) << 4);
            ldsm4(bh[0], bh[1], bh[2], bh[3], sb + SB2H + off);
            ldsm4(bl[0], bl[1], bl[2], bl[3], sb + SB2L + off);
            #pragma unroll
            for (int mb = 0; mb < 2; mb++) {
                #pragma unroll
                for (int nt = 0; nt < 2; nt++) {
                    uint32_t h0 = nt ? bh[1] : bh[0], h1 = nt ? bh[3] : bh[2];
                    uint32_t q0 = nt ? bl[1] : bl[0], q1 = nt ? bl[3] : bl[2];
                    mma16816(acc[mb][nt], ch[mb][kb], h0, h1);
                    mma16816(acc[mb][nt], ch[mb][kb], q0, q1);
                    mma16816(acc[mb][nt], cl[mb][kb], h0, h1);
                }
            }
        }
        // epilogue: re-read A fp32 (L2-hot), subtract, store
        #pragma unroll
        for (int mb = 0; mb < 2; mb++) {
            #pragma unroll
            for (int nt = 0; nt < 2; nt++) {
                int col = nc16 * 16 + nt * 8 + ((lane & 3) << 1);
                #pragma unroll
                for (int h = 0; h < 2; h++) {
                    int r = mrow + mb * 16 + rl + h * 8;
                    const float* ap = Abase + (size_t)r * DDIM + col;
                    float2 av = *(const float2*)ap;
                    float2 o;
                    o.x = av.x - acc[mb][nt][h * 2 + 0];
                    o.y = av.y - acc[mb][nt][h * 2 + 1];
                    *(float2*)(Obase + (size_t)r * DDIM + col) = o;
                }
            }
        }
    }
}

extern "C" void kernel_launch(void* const* d_in, const int* in_sizes, int n_in,
                              void* d_out, int out_size) {
    const float* inp = (const float*)d_in[0];   // inputs  [N, 256]
    const float* qv  = (const float*)d_in[1];   // q_vectors [32, 256]
    float* out = (float*)d_out;

    int n_rows = in_sizes[0] / DDIM;
    int n_tiles = n_rows / MT;

    cudaFuncSetAttribute(hh_main, cudaFuncAttributeMaxDynamicSharedMemorySize, SMEM_TOTAL);

    long long nd = (long long)n_rows * DDIM;
    long long total = (long long)out_size;

    setup_all<<<1, 256>>>(qv);
    hh_main<<<n_tiles, 256, SMEM_TOTAL>>>(inp, out, nd, total);
}

// round 8
// speedup vs baseline: 1.9541x; 1.0766x over previous
#include <cuda_runtime.h>
#include <cuda_bf16.h>
#include <cstdint>

#define DDIM 256
#define KREF 32
#define MT   256    // rows per CTA (8 warps x m32)

// ---------------- device scratch (no allocation) ----------------
__device__ __align__(16) __nv_bfloat16 g_Uh[KREF * DDIM];   // [k][d]
__device__ __align__(16) __nv_bfloat16 g_Ul[KREF * DDIM];
__device__ __align__(16) __nv_bfloat16 g_Qh[DDIM * KREF];   // [d][k]
__device__ __align__(16) __nv_bfloat16 g_Ql[DDIM * KREF];

// ---------------- helpers ----------------
__device__ __forceinline__ uint32_t smem_u32(const void* p) {
    uint32_t a;
    asm("{ .reg .u64 t; cvta.to.shared.u64 t, %1; cvt.u32.u64 %0, t; }" : "=r"(a) : "l"(p));
    return a;
}
__device__ __forceinline__ void ldsm4(uint32_t& r0, uint32_t& r1, uint32_t& r2, uint32_t& r3,
                                      uint32_t addr) {
    asm volatile("ldmatrix.sync.aligned.m8n8.x4.shared.b16 {%0,%1,%2,%3}, [%4];"
                 : "=r"(r0), "=r"(r1), "=r"(r2), "=r"(r3) : "r"(addr));
}
__device__ __forceinline__ void mma16816(float* d, const uint32_t* a, uint32_t b0, uint32_t b1) {
    asm volatile(
        "mma.sync.aligned.m16n8k16.row.col.f32.bf16.bf16.f32 "
        "{%0,%1,%2,%3},{%4,%5,%6,%7},{%8,%9},{%0,%1,%2,%3};"
        : "+f"(d[0]), "+f"(d[1]), "+f"(d[2]), "+f"(d[3])
        : "r"(a[0]), "r"(a[1]), "r"(a[2]), "r"(a[3]), "r"(b0), "r"(b1));
}
__device__ __forceinline__ uint32_t pack_bf16x2(float x, float y) {
    __nv_bfloat162 p = __halves2bfloat162(__float2bfloat16(x), __float2bfloat16(y));
    return *reinterpret_cast<uint32_t*>(&p);
}
__device__ __forceinline__ void split2f(float x, float y, uint32_t& hi, uint32_t& lo) {
    hi = pack_bf16x2(x, y);
    __nv_bfloat162 hb = *reinterpret_cast<__nv_bfloat162*>(&hi);
    lo = pack_bf16x2(x - __low2float(hb), y - __high2float(hb));
}
__device__ __forceinline__ void split2(float2 v, uint32_t& hi, uint32_t& lo) {
    split2f(v.x, v.y, hi, lo);
}

// Exchange a float4 row segment within lane pairs (xor 1) to build mma frag pairs.
// Thread quad ownership: q0->cols0-3, q1->cols8-11, q2->cols4-7, q3->cols12-15.
// Output: f0 = cols (2q,2q+1), f1 = cols (2q+8,2q+9).
__device__ __forceinline__ void xchg_frags(float4 v, int qodd,
                                           float2& f0, float2& f1) {
    float sx = qodd ? v.x : v.z;
    float sy = qodd ? v.y : v.w;
    float rx = __shfl_xor_sync(0xFFFFFFFFu, sx, 1);
    float ry = __shfl_xor_sync(0xFFFFFFFFu, sy, 1);
    f0.x = qodd ? rx : v.x;  f0.y = qodd ? ry : v.y;
    f1.x = qodd ? v.z : rx;  f1.y = qodd ? v.w : ry;
}

// ---------------- setup (single kernel, W stays in registers) ----------------
__global__ void __launch_bounds__(256) setup_all(const float* __restrict__ qv) {
    __shared__ float qs[KREF][DDIM];
    __shared__ float G[KREF][KREF];
    __shared__ float cinv[KREF];
    int t = threadIdx.x;
    for (int i = t; i < KREF * DDIM; i += 256) qs[i >> 8][i & 255] = qv[i];
    __syncthreads();
    #pragma unroll
    for (int p = 0; p < 4; p++) {
        int idx = t + p * 256;
        int j = idx >> 5, k = idx & 31;
        float s = 0.f;
        #pragma unroll 8
        for (int d = 0; d < DDIM; d++) s = fmaf(qs[j][d], qs[k][d], s);
        G[j][k] = s;
    }
    __syncthreads();
    if (t < KREF) cinv[t] = 2.0f / G[t][t];
    __syncthreads();

    float w[KREF];
    const int d = t;
    #pragma unroll
    for (int k = 0; k < KREF; k++) {
        float acc = qs[k][d];
        #pragma unroll
        for (int j = 0; j < KREF; j++)
            if (j < k) acc = fmaf(-G[j][k], w[j], acc);
        w[k] = cinv[k] * acc;
    }
    #pragma unroll
    for (int k = 0; k < KREF; k++) {
        float wv = w[k];
        __nv_bfloat16 wh = __float2bfloat16(wv);
        g_Uh[k * DDIM + d] = wh;
        g_Ul[k * DDIM + d] = __float2bfloat16(wv - __bfloat162float(wh));
        float q = qs[k][d];
        __nv_bfloat16 qh = __float2bfloat16(q);
        g_Qh[d * KREF + k] = qh;
        g_Ql[d * KREF + k] = __float2bfloat16(q - __bfloat162float(qh));
    }
}

// ---------------- SMEM layout (bytes) ----------------
#define SB1H 0
#define SB1L 16384
#define SB2H 32768
#define SB2L 49152
#define SMEM_TOTAL 65536

__global__ void __launch_bounds__(256, 2)
hh_main(const float* __restrict__ in, float* __restrict__ out,
        long long nd, long long total) {
    extern __shared__ char smem[];
    const uint32_t sb = smem_u32(smem);
    const int tid = threadIdx.x;
    const int wid = tid >> 5, lane = tid & 31;
    const int tile = blockIdx.x;

    const float* Abase = in + (size_t)tile * MT * DDIM;
    float* Obase = out + (size_t)tile * MT * DDIM;

    // ---- zero my slice of the tail (logabsdet) ----
    {
        long long tail = total - nd;
        int ntile = (int)gridDim.x;
        long long per = (tail + ntile - 1) / ntile;
        long long start = nd + (long long)tile * per;
        for (long long j = tid; j < per; j += 256) {
            long long idx = start + j;
            if (idx < total) out[idx] = 0.0f;
        }
    }

    // ---- stage B1 (U hi/lo): 32x256 bf16 each ----
    #pragma unroll
    for (int i = 0; i < 8; i++) {
        int idx4 = tid + i * 256;
        int row = idx4 >> 6;
        int j4 = (idx4 & 63) << 2;
        uint32_t off = row * 512u + ((((uint32_t)(j4 >> 3)) ^ (row & 7)) << 4) + ((j4 & 4) << 1);
        *(uint2*)(smem + SB1H + off) = *(const uint2*)(g_Uh + row * DDIM + j4);
        *(uint2*)(smem + SB1L + off) = *(const uint2*)(g_Ul + row * DDIM + j4);
    }
    // ---- stage B2 (qT hi/lo): 256x32 bf16 each ----
    #pragma unroll
    for (int i = 0; i < 8; i++) {
        int idx4 = tid + i * 256;
        int row = idx4 >> 3;
        int j4 = (idx4 & 7) << 2;
        uint32_t off = row * 64u + ((((uint32_t)(j4 >> 3)) ^ ((row >> 1) & 3)) << 4) + ((j4 & 4) << 1);
        *(uint2*)(smem + SB2H + off) = *(const uint2*)(g_Qh + row * KREF + j4);
        *(uint2*)(smem + SB2L + off) = *(const uint2*)(g_Ql + row * KREF + j4);
    }
    __syncthreads();

    // ========== GEMM1: C[256x32] = A * U^T, each warp m32 (2 m16 blocks) ==========
    const int mrow = wid * 32;
    const int rl = lane >> 2;
    const int q = lane & 3;
    const int qodd = q & 1;
    const int coff = ((q & 1) << 3) | ((q >> 1) << 2);   // 0,8,4,12

    // row pointers for the 4 fragment rows (mb in {0,1}, +0/+8)
    const float* Ar[2];
    Ar[0] = Abase + (size_t)(mrow + rl) * DDIM + coff;
    Ar[1] = Ar[0] + 16 * DDIM;

    float accC[2][4][4];
    #pragma unroll
    for (int mb = 0; mb < 2; mb++)
        #pragma unroll
        for (int nt = 0; nt < 4; nt++)
            #pragma unroll
            for (int j = 0; j < 4; j++) accC[mb][nt][j] = 0.f;

    float4 pv[2][2];   // [mb][row(0/+8)]
    #pragma unroll
    for (int mb = 0; mb < 2; mb++) {
        pv[mb][0] = *(const float4*)(Ar[mb]);
        pv[mb][1] = *(const float4*)(Ar[mb] + 8 * DDIM);
    }

    #pragma unroll
    for (int ks = 0; ks < 16; ks++) {
        float4 cv[2][2];
        #pragma unroll
        for (int mb = 0; mb < 2; mb++) { cv[mb][0] = pv[mb][0]; cv[mb][1] = pv[mb][1]; }
        if (ks < 15) {
            #pragma unroll
            for (int mb = 0; mb < 2; mb++) {
                pv[mb][0] = *(const float4*)(Ar[mb] + (ks + 1) * 16);
                pv[mb][1] = *(const float4*)(Ar[mb] + (ks + 1) * 16 + 8 * DDIM);
            }
        }

        uint32_t ah[2][4], al[2][4];
        #pragma unroll
        for (int mb = 0; mb < 2; mb++) {
            float2 f00, f01, f10, f11;
            xchg_frags(cv[mb][0], qodd, f00, f01);   // row r:   frag(2q), frag(2q+8)
            xchg_frags(cv[mb][1], qodd, f10, f11);   // row r+8
            split2(f00, ah[mb][0], al[mb][0]);
            split2(f10, ah[mb][1], al[mb][1]);
            split2(f01, ah[mb][2], al[mb][2]);
            split2(f11, ah[mb][3], al[mb][3]);
        }

        uint32_t bh[2][4], bl[2][4];
        #pragma unroll
        for (int t2 = 0; t2 < 2; t2++) {
            int n = t2 * 16 + (lane & 15);
            uint32_t ch = (uint32_t)(ks * 2 + (lane >> 4));
            uint32_t off = n * 512u + ((ch ^ (n & 7)) << 4);
            ldsm4(bh[t2][0], bh[t2][1], bh[t2][2], bh[t2][3], sb + SB1H + off);
            ldsm4(bl[t2][0], bl[t2][1], bl[t2][2], bl[t2][3], sb + SB1L + off);
        }
        #pragma unroll
        for (int mb = 0; mb < 2; mb++) {
            #pragma unroll
            for (int nt = 0; nt < 4; nt++) {
                const uint32_t* Bh = bh[nt >> 1];
                const uint32_t* Bl = bl[nt >> 1];
                uint32_t h0 = (nt & 1) ? Bh[1] : Bh[0], h1 = (nt & 1) ? Bh[3] : Bh[2];
                uint32_t q0 = (nt & 1) ? Bl[1] : Bl[0], q1 = (nt & 1) ? Bl[3] : Bl[2];
                mma16816(accC[mb][nt], ah[mb], h0, h1);
                mma16816(accC[mb][nt], ah[mb], q0, q1);
                mma16816(accC[mb][nt], al[mb], h0, h1);
            }
        }
    }

    // ---- repack C (acc layout == GEMM2 A-fragment layout, k = n) ----
    uint32_t ch[2][2][4], cl[2][2][4];
    #pragma unroll
    for (int mb = 0; mb < 2; mb++) {
        #pragma unroll
        for (int kb = 0; kb < 2; kb++) {
            split2f(accC[mb][kb * 2][0],     accC[mb][kb * 2][1],     ch[mb][kb][0], cl[mb][kb][0]);
            split2f(accC[mb][kb * 2][2],     accC[mb][kb * 2][3],     ch[mb][kb][1], cl[mb][kb][1]);
            split2f(accC[mb][kb * 2 + 1][0], accC[mb][kb * 2 + 1][1], ch[mb][kb][2], cl[mb][kb][2]);
            split2f(accC[mb][kb * 2 + 1][2], accC[mb][kb * 2 + 1][3], ch[mb][kb][3], cl[mb][kb][3]);
        }
    }

    // ========== GEMM2 + epilogue: out = A - C * Q^T ==========
    #pragma unroll 1
    for (int nc16 = 0; nc16 < 16; nc16++) {
        float acc[2][2][4];
        #pragma unroll
        for (int mb = 0; mb < 2; mb++)
            #pragma unroll
            for (int nt = 0; nt < 2; nt++)
                #pragma unroll
                for (int j = 0; j < 4; j++) acc[mb][nt][j] = 0.f;

        #pragma unroll
        for (int kb = 0; kb < 2; kb++) {
            uint32_t bh[4], bl[4];
            int n = nc16 * 16 + (lane & 15);
            uint32_t chn = (uint32_t)(kb * 2 + (lane >> 4));
            uint32_t off = n * 64u + ((chn ^ ((n >> 1) & 3)) << 4);
            ldsm4(bh[0], bh[1], bh[2], bh[3], sb + SB2H + off);
            ldsm4(bl[0], bl[1], bl[2], bl[3], sb + SB2L + off);
            #pragma unroll
            for (int mb = 0; mb < 2; mb++) {
                #pragma unroll
                for (int nt = 0; nt < 2; nt++) {
                    uint32_t h0 = nt ? bh[1] : bh[0], h1 = nt ? bh[3] : bh[2];
                    uint32_t q0 = nt ? bl[1] : bl[0], q1 = nt ? bl[3] : bl[2];
                    mma16816(acc[mb][nt], ch[mb][kb], h0, h1);
                    mma16816(acc[mb][nt], ch[mb][kb], q0, q1);
                    mma16816(acc[mb][nt], cl[mb][kb], h0, h1);
                }
            }
        }
        // epilogue: float4 A re-read + shfl exchange; float4 store via shfl gather
        #pragma unroll
        for (int mb = 0; mb < 2; mb++) {
            #pragma unroll
            for (int h = 0; h < 2; h++) {
                int r = mrow + mb * 16 + rl + h * 8;
                const float* ap = Abase + (size_t)r * DDIM + nc16 * 16 + coff;
                float4 v = *(const float4*)ap;
                float2 a0, a1;
                xchg_frags(v, qodd, a0, a1);
                float o0x = a0.x - acc[mb][0][h * 2 + 0];
                float o0y = a0.y - acc[mb][0][h * 2 + 1];
                float o1x = a1.x - acc[mb][1][h * 2 + 0];
                float o1y = a1.y - acc[mb][1][h * 2 + 1];
                // gather for STG.128: even sends o1, odd sends o0
                float tx = qodd ? o0x : o1x;
                float ty = qodd ? o0y : o1y;
                float ux = __shfl_xor_sync(0xFFFFFFFFu, tx, 1);
                float uy = __shfl_xor_sync(0xFFFFFFFFu, ty, 1);
                float4 o;
                o.x = qodd ? ux : o0x;
                o.y = qodd ? uy : o0y;
                o.z = qodd ? o1x : ux;
                o.w = qodd ? o1y : uy;
                *(float4*)(Obase + (size_t)r * DDIM + nc16 * 16 + coff) = o;
            }
        }
    }
}

extern "C" void kernel_launch(void* const* d_in, const int* in_sizes, int n_in,
                              void* d_out, int out_size) {
    const float* inp = (const float*)d_in[0];   // inputs  [N, 256]
    const float* qv  = (const float*)d_in[1];   // q_vectors [32, 256]
    float* out = (float*)d_out;

    int n_rows = in_sizes[0] / DDIM;
    int n_tiles = n_rows / MT;

    cudaFuncSetAttribute(hh_main, cudaFuncAttributeMaxDynamicSharedMemorySize, SMEM_TOTAL);

    long long nd = (long long)n_rows * DDIM;
    long long total = (long long)out_size;

    setup_all<<<1, 256>>>(qv);
    hh_main<<<n_tiles, 256, SMEM_TOTAL>>>(inp, out, nd, total);
}